// round 17
// baseline (speedup 1.0000x reference)
#include <cuda_runtime.h>
#include <cuda_bf16.h>
#include <cstdint>

// ---------------------------------------------------------------------------
// Problem constants
// ---------------------------------------------------------------------------
#define BATCHN  8
#define SEQL    1024
#define EMB     768
#define NH      12
#define HD      64
#define ROWS    (BATCHN*SEQL)        // 8192
#define QKVC    (3*EMB)              // 2304
#define ZTOT    (BATCHN*NH)          // 96
#define AROWS   (ZTOT*SEQL)          // 98304
#define K_SCALE 0.125f
#define EXP_OFF 20.0f

// ---------------------------------------------------------------------------
// Device scratch (static globals; allocation-free)
// ---------------------------------------------------------------------------
__device__ __align__(16) __nv_bfloat16 g_x_hi  [ROWS*EMB];
__device__ __align__(16) __nv_bfloat16 g_x_lo  [ROWS*EMB];
__device__ __align__(16) __nv_bfloat16 g_wqkv_hi[QKVC*EMB];
__device__ __align__(16) __nv_bfloat16 g_wqkv_lo[QKVC*EMB];
__device__ __align__(16) __nv_bfloat16 g_wp_hi [EMB*EMB];
__device__ __align__(16) __nv_bfloat16 g_wp_lo [EMB*EMB];
__device__ __align__(16) __nv_bfloat16 g_qkv_hi[(size_t)ROWS*QKVC];
__device__ __align__(16) __nv_bfloat16 g_qkv_lo[(size_t)ROWS*QKVC];
__device__ __align__(16) __nv_bfloat16 g_oh_hi [ROWS*EMB];
__device__ __align__(16) __nv_bfloat16 g_oh_lo [ROWS*EMB];
__device__ float g_inv [AROWS];

// ---------------------------------------------------------------------------
// PTX helpers (all sm_80-era: safe on plain compute_103)
// ---------------------------------------------------------------------------
__device__ __forceinline__ uint32_t smem_u32(const void* p) {
    uint32_t a;
    asm("{ .reg .u64 t; cvta.to.shared.u64 t, %1; cvt.u32.u64 %0, t; }"
        : "=r"(a) : "l"(p));
    return a;
}
__device__ __forceinline__ void cp16(uint32_t dst, const void* src) {
    asm volatile("cp.async.cg.shared.global [%0], [%1], 16;"
                 :: "r"(dst), "l"(src));
}
#define CP_COMMIT() asm volatile("cp.async.commit_group;" ::: "memory")
#define CP_WAIT(n)  asm volatile("cp.async.wait_group %0;" :: "n"(n) : "memory")

__device__ __forceinline__ void ldsm_x4(uint32_t* r, uint32_t addr) {
    asm volatile("ldmatrix.sync.aligned.m8n8.x4.shared.b16 {%0,%1,%2,%3}, [%4];"
        : "=r"(r[0]), "=r"(r[1]), "=r"(r[2]), "=r"(r[3]) : "r"(addr));
}
__device__ __forceinline__ void ldsm_x2(uint32_t* r, uint32_t addr) {
    asm volatile("ldmatrix.sync.aligned.m8n8.x2.shared.b16 {%0,%1}, [%2];"
        : "=r"(r[0]), "=r"(r[1]) : "r"(addr));
}
__device__ __forceinline__ void ldsm_x2t(uint32_t* r, uint32_t addr) {
    asm volatile("ldmatrix.sync.aligned.m8n8.x2.trans.shared.b16 {%0,%1}, [%2];"
        : "=r"(r[0]), "=r"(r[1]) : "r"(addr));
}
__device__ __forceinline__ void mma_bf16(float* c, const uint32_t* a, const uint32_t* b) {
    asm volatile("mma.sync.aligned.m16n8k16.row.col.f32.bf16.bf16.f32 "
        "{%0,%1,%2,%3}, {%4,%5,%6,%7}, {%8,%9}, {%0,%1,%2,%3};"
        : "+f"(c[0]), "+f"(c[1]), "+f"(c[2]), "+f"(c[3])
        : "r"(a[0]), "r"(a[1]), "r"(a[2]), "r"(a[3]), "r"(b[0]), "r"(b[1]));
}

__device__ __forceinline__ uint32_t pack_hi(float a, float b) {
    return ((uint32_t)__bfloat16_as_ushort(__float2bfloat16(b)) << 16) |
            (uint32_t)__bfloat16_as_ushort(__float2bfloat16(a));
}
__device__ __forceinline__ uint32_t pack_lo(float a, float b) {
    __nv_bfloat16 ha = __float2bfloat16(a), hb = __float2bfloat16(b);
    float la = a - __bfloat162float(ha), lb = b - __bfloat162float(hb);
    return ((uint32_t)__bfloat16_as_ushort(__float2bfloat16(lb)) << 16) |
            (uint32_t)__bfloat16_as_ushort(__float2bfloat16(la));
}
// fp32 pair -> (hi bf16x2, lo bf16x2); identical rounding to pack_hi/pack_lo
__device__ __forceinline__ void split2(float p0, float p1, uint32_t& hi, uint32_t& lo) {
    asm("cvt.rn.bf16x2.f32 %0, %1, %2;" : "=r"(hi) : "f"(p1), "f"(p0));
    float h0 = __uint_as_float(hi << 16);
    float h1 = __uint_as_float(hi & 0xffff0000u);
    float l0 = p0 - h0;
    float l1 = p1 - h1;
    asm("cvt.rn.bf16x2.f32 %0, %1, %2;" : "=r"(lo) : "f"(l1), "f"(l0));
}

// ---------------------------------------------------------------------------
// BIG-TILE projection GEMM (modes 0 and 3). Unchanged (proven).
// ---------------------------------------------------------------------------
template<int MODE>
__global__ __launch_bounds__(256)
void gemm_big(const __nv_bfloat16* __restrict__ Ahi_base,
              const __nv_bfloat16* __restrict__ Alo_base,
              const __nv_bfloat16* __restrict__ Bhi_base,
              const __nv_bfloat16* __restrict__ Blo_base,
              float* __restrict__ fout,
              __nv_bfloat16* __restrict__ ohi,
              __nv_bfloat16* __restrict__ olo,
              const float* __restrict__ bias,
              int by0) {
    constexpr int NSTAGE  = EMB / 32;           // 24
    constexpr int STAGES  = 3;
    constexpr int LDS     = 40;
    constexpr int A_BYTES = 256 * LDS * 2;
    constexpr int B_BYTES = 128 * LDS * 2;
    constexpr int STAGE_B = 2 * A_BYTES + 2 * B_BYTES;

    extern __shared__ __align__(16) char dynsmem[];

    const int tid  = threadIdx.x;
    const int lane = tid & 31;
    const int wid  = tid >> 5;
    const int wm   = wid & 3;
    const int wn   = wid >> 2;
    const int l15  = lane & 15;
    const int bx = blockIdx.x, by = blockIdx.y + by0;

    const __nv_bfloat16* Ah = Ahi_base + (long long)by * 256 * EMB;
    const __nv_bfloat16* Al = Alo_base + (long long)by * 256 * EMB;
    const __nv_bfloat16* Bh = Bhi_base + (long long)bx * 128 * EMB;
    const __nv_bfloat16* Bl = Blo_base + (long long)bx * 128 * EMB;

    const int arow = tid >> 2;
    const int acol = (tid & 3) * 8;

    const uint32_t sb = smem_u32(dynsmem);

    auto issue = [&](int s) {
        const uint32_t base = sb + (uint32_t)(s % STAGES) * STAGE_B;
        const long long k0 = (long long)s * 32;
        #pragma unroll
        for (int it = 0; it < 4; it++) {
            const int r = arow + it * 64;
            const uint32_t d = base + (uint32_t)(r * LDS + acol) * 2;
            cp16(d,           Ah + (long long)r * EMB + k0 + acol);
            cp16(d + A_BYTES, Al + (long long)r * EMB + k0 + acol);
        }
        #pragma unroll
        for (int it = 0; it < 2; it++) {
            const int r = arow + it * 64;
            const uint32_t d = base + 2 * A_BYTES + (uint32_t)(r * LDS + acol) * 2;
            cp16(d,           Bh + (long long)r * EMB + k0 + acol);
            cp16(d + B_BYTES, Bl + (long long)r * EMB + k0 + acol);
        }
    };

    float acc[4][8][4];
    #pragma unroll
    for (int i = 0; i < 4; i++)
        #pragma unroll
        for (int j = 0; j < 8; j++)
            #pragma unroll
            for (int e = 0; e < 4; e++) acc[i][j][e] = 0.f;

    issue(0); CP_COMMIT();
    issue(1); CP_COMMIT();

    for (int s = 0; s < NSTAGE; s++) {
        CP_WAIT(1);
        __syncthreads();
        if (s + 2 < NSTAGE) issue(s + 2);
        CP_COMMIT();

        const uint32_t base = sb + (uint32_t)(s % STAGES) * STAGE_B;
        const uint32_t uAh = base;
        const uint32_t uAl = base + A_BYTES;
        const uint32_t uBh = base + 2 * A_BYTES;
        const uint32_t uBl = base + 2 * A_BYTES + B_BYTES;

        #pragma unroll
        for (int ks = 0; ks < 2; ks++) {
            uint32_t bh[8][2], bl[8][2];
            #pragma unroll
            for (int j = 0; j < 8; j++) {
                const int nr = wn * 64 + j * 8 + (l15 & 7);
                const int kc = ks * 16 + (l15 >> 3) * 8;
                const uint32_t off = (uint32_t)(nr * LDS + kc) * 2;
                ldsm_x2(bh[j], uBh + off);
                ldsm_x2(bl[j], uBl + off);
            }
            #pragma unroll
            for (int i = 0; i < 4; i++) {
                const int ar = wm * 64 + i * 16 + l15;
                const int ac = ks * 16 + (lane >> 4) * 8;
                const uint32_t aoff = (uint32_t)(ar * LDS + ac) * 2;
                uint32_t ah[4], al[4];
                ldsm_x4(ah, uAh + aoff);
                #pragma unroll
                for (int j = 0; j < 8; j++) mma_bf16(acc[i][j], ah, bh[j]);
                ldsm_x4(al, uAl + aoff);
                #pragma unroll
                for (int j = 0; j < 8; j++) mma_bf16(acc[i][j], ah, bl[j]);
                #pragma unroll
                for (int j = 0; j < 8; j++) mma_bf16(acc[i][j], al, bh[j]);
            }
        }
    }

    const int g = lane >> 2, t = lane & 3;
    #pragma unroll
    for (int i = 0; i < 4; i++) {
        const int m0 = by * 256 + wm * 64 + i * 16 + g;
        const int m1 = m0 + 8;
        #pragma unroll
        for (int j = 0; j < 8; j++) {
            const int n = bx * 128 + wn * 64 + j * 8 + 2 * t;
            const float c0 = acc[i][j][0], c1 = acc[i][j][1];
            const float c2 = acc[i][j][2], c3 = acc[i][j][3];
            if (MODE == 0) {
                long long o0 = (long long)m0 * QKVC + n;
                long long o1 = (long long)m1 * QKVC + n;
                *(uint32_t*)(ohi + o0) = pack_hi(c0, c1);
                *(uint32_t*)(olo + o0) = pack_lo(c0, c1);
                *(uint32_t*)(ohi + o1) = pack_hi(c2, c3);
                *(uint32_t*)(olo + o1) = pack_lo(c2, c3);
            } else {
                float2 w0 = { c0 + bias[n], c1 + bias[n + 1] };
                float2 w1 = { c2 + bias[n], c3 + bias[n + 1] };
                *(float2*)(fout + (long long)m0 * EMB + n) = w0;
                *(float2*)(fout + (long long)m1 * EMB + n) = w1;
            }
        }
    }
}

// ---------------------------------------------------------------------------
// FUSED attention: S=Q K^T, p=exp (unnormalized fp32 -> attn), rowsum,
// O += P V (in-register fragment conversion). Writes per-row inv to g_inv;
// attn normalization deferred to norm_attn (overlaps out-projection).
// ---------------------------------------------------------------------------
#define LDSQ 72
#define STG_LDS 66

__global__ __launch_bounds__(256, 2)
void fused_attn(const __nv_bfloat16* __restrict__ Qhi,
                const __nv_bfloat16* __restrict__ Qlo,
                float* __restrict__ attn,
                __nv_bfloat16* __restrict__ ohi,
                __nv_bfloat16* __restrict__ olo,
                float* __restrict__ invout,
                int z0) {
    constexpr int NCHUNK  = 16;
    constexpr int QBUF    = 128 * LDSQ * 2;     // 18432
    constexpr int KVBUF   = 64 * LDSQ * 2;      // 9216
    constexpr int STAGE_B = 4 * KVBUF;          // 36864
    constexpr int KV0     = 2 * QBUF;           // 36864

    extern __shared__ __align__(16) char dynsmem[];

    const int tid  = threadIdx.x;
    const int lane = tid & 31;
    const int wid  = tid >> 5;
    const int l15  = lane & 15;
    const int g    = lane >> 2;
    const int t    = lane & 3;
    const int by = blockIdx.x;
    const int bz = blockIdx.y + z0;
    const int bb = bz / NH, hh = bz % NH;

    const long long qrow0 = (long long)bb * SEQL + by * 128;
    const long long krow0 = (long long)bb * SEQL;
    float* attn_z = attn + (long long)bz * SEQL * SEQL;

    const uint32_t sb = smem_u32(dynsmem);

    const int lrow = tid >> 3;
    const int lc16 = (tid & 7);

    auto issueQ = [&]() {
        #pragma unroll
        for (int it = 0; it < 4; it++) {
            const int r = lrow + it * 32;
            const long long go = (qrow0 + r) * QKVC + hh * HD + lc16 * 8;
            const uint32_t d = sb + (uint32_t)(r * LDSQ + lc16 * 8) * 2;
            cp16(d,        Qhi + go);
            cp16(d + QBUF, Qlo + go);
        }
    };
    auto issueKV = [&](int c) {
        const uint32_t base = sb + KV0 + (uint32_t)(c & 1) * STAGE_B;
        #pragma unroll
        for (int it = 0; it < 2; it++) {
            const int r = lrow + it * 32;
            const long long gk = (krow0 + c * 64 + r) * QKVC + EMB + hh * HD + lc16 * 8;
            const long long gv = gk + EMB;
            const uint32_t d = base + (uint32_t)(r * LDSQ + lc16 * 8) * 2;
            cp16(d,             Qhi + gk);
            cp16(d + KVBUF,     Qlo + gk);
            cp16(d + 2 * KVBUF, Qhi + gv);
            cp16(d + 3 * KVBUF, Qlo + gv);
        }
    };

    float o_acc[8][4];
    #pragma unroll
    for (int n = 0; n < 8; n++)
        #pragma unroll
        for (int e = 0; e < 4; e++) o_acc[n][e] = 0.f;
    float rs0 = 0.f, rs1 = 0.f;

    issueQ(); issueKV(0); CP_COMMIT();
    issueKV(1); CP_COMMIT();

    const uint32_t uQh = sb;
    const uint32_t uQl = sb + QBUF;

    for (int c = 0; c < NCHUNK; c++) {
        CP_WAIT(1);
        __syncthreads();

        const uint32_t base = sb + KV0 + (uint32_t)(c & 1) * STAGE_B;
        const uint32_t uKh = base;
        const uint32_t uKl = base + KVBUF;
        const uint32_t uVh = base + 2 * KVBUF;
        const uint32_t uVl = base + 3 * KVBUF;

        // ---- S = Q K^T, 3-term ----
        float s_acc[8][4];
        #pragma unroll
        for (int n = 0; n < 8; n++)
            #pragma unroll
            for (int e = 0; e < 4; e++) s_acc[n][e] = 0.f;

        #pragma unroll
        for (int ks = 0; ks < 4; ks++) {
            const int ar = wid * 16 + l15;
            const int ac = ks * 16 + (lane >> 4) * 8;
            const uint32_t aoff = (uint32_t)(ar * LDSQ + ac) * 2;
            uint32_t ah[4], al[4];
            ldsm_x4(ah, uQh + aoff);
            ldsm_x4(al, uQl + aoff);
            #pragma unroll
            for (int j = 0; j < 8; j++) {
                const int nr = j * 8 + (l15 & 7);
                const int kc = ks * 16 + (l15 >> 3) * 8;
                const uint32_t off = (uint32_t)(nr * LDSQ + kc) * 2;
                uint32_t bh[2], bl[2];
                ldsm_x2(bh, uKh + off);
                ldsm_x2(bl, uKl + off);
                mma_bf16(s_acc[j], ah, bh);
                mma_bf16(s_acc[j], ah, bl);
                mma_bf16(s_acc[j], al, bh);
            }
        }

        // ---- p = exp, rowsum, store unnormalized fp32 P ----
        const int r0 = by * 128 + wid * 16 + g;
        #pragma unroll
        for (int j = 0; j < 8; j++) {
            float p0 = __expf(fmaf(s_acc[j][0], K_SCALE, -EXP_OFF));
            float p1 = __expf(fmaf(s_acc[j][1], K_SCALE, -EXP_OFF));
            float p2 = __expf(fmaf(s_acc[j][2], K_SCALE, -EXP_OFF));
            float p3 = __expf(fmaf(s_acc[j][3], K_SCALE, -EXP_OFF));
            rs0 += p0 + p1; rs1 += p2 + p3;
            s_acc[j][0] = p0; s_acc[j][1] = p1;
            s_acc[j][2] = p2; s_acc[j][3] = p3;
            const long long col = (long long)c * 64 + j * 8 + 2 * t;
            float2 w0 = { p0, p1 }, w1 = { p2, p3 };
            *(float2*)(attn_z + (long long)r0 * SEQL + col)       = w0;
            *(float2*)(attn_z + (long long)(r0 + 8) * SEQL + col) = w1;
        }

        // ---- O += P V, 3-term; P A-frags from accumulator frags ----
        #pragma unroll
        for (int jp = 0; jp < 4; jp++) {
            uint32_t ah[4], al[4];
            split2(s_acc[2*jp][0],   s_acc[2*jp][1],   ah[0], al[0]);
            split2(s_acc[2*jp][2],   s_acc[2*jp][3],   ah[1], al[1]);
            split2(s_acc[2*jp+1][0], s_acc[2*jp+1][1], ah[2], al[2]);
            split2(s_acc[2*jp+1][2], s_acc[2*jp+1][3], ah[3], al[3]);
            #pragma unroll
            for (int n = 0; n < 8; n++) {
                const int kr = jp * 16 + l15;
                const uint32_t off = (uint32_t)(kr * LDSQ + n * 8) * 2;
                uint32_t bvh[2], bvl[2];
                ldsm_x2t(bvh, uVh + off);
                ldsm_x2t(bvl, uVl + off);
                mma_bf16(o_acc[n], ah, bvh);
                mma_bf16(o_acc[n], ah, bvl);
                mma_bf16(o_acc[n], al, bvh);
            }
        }

        __syncthreads();
        if (c + 2 < NCHUNK) issueKV(c + 2);
        CP_COMMIT();
    }

    // ---- rowsum reduce over quad; publish inv to gmem ----
    rs0 += __shfl_xor_sync(0xffffffffu, rs0, 1);
    rs0 += __shfl_xor_sync(0xffffffffu, rs0, 2);
    rs1 += __shfl_xor_sync(0xffffffffu, rs1, 1);
    rs1 += __shfl_xor_sync(0xffffffffu, rs1, 2);
    const float inv0 = 1.0f / rs0;
    const float inv1 = 1.0f / rs1;
    if (t == 0) {
        const long long ib = (long long)bz * SEQL + by * 128 + wid * 16 + g;
        invout[ib]     = inv0;
        invout[ib + 8] = inv1;
    }

    // ---- oh epilogue: stage hi/lo in smem, coalesced store ----
    CP_WAIT(0);
    __syncthreads();
    __nv_bfloat16* sOh = (__nv_bfloat16*)dynsmem;
    __nv_bfloat16* sOl = sOh + 128 * STG_LDS;
    #pragma unroll
    for (int n = 0; n < 8; n++) {
        const int r0 = wid * 16 + g;
        const float v0 = o_acc[n][0] * inv0, v1 = o_acc[n][1] * inv0;
        const float v2 = o_acc[n][2] * inv1, v3 = o_acc[n][3] * inv1;
        const int nloc = n * 8 + 2 * t;
        *(uint32_t*)(sOh + r0 * STG_LDS + nloc)       = pack_hi(v0, v1);
        *(uint32_t*)(sOl + r0 * STG_LDS + nloc)       = pack_lo(v0, v1);
        *(uint32_t*)(sOh + (r0 + 8) * STG_LDS + nloc) = pack_hi(v2, v3);
        *(uint32_t*)(sOl + (r0 + 8) * STG_LDS + nloc) = pack_lo(v2, v3);
    }
    __syncthreads();

    #pragma unroll
    for (int k = 0; k < 16; k++) {
        const int idx  = tid + k * 256;
        const int row  = idx >> 5;
        const int word = idx & 31;
        const uint32_t wh = *(const uint32_t*)(sOh + row * STG_LDS + word * 2);
        const uint32_t wl = *(const uint32_t*)(sOl + row * STG_LDS + word * 2);
        long long gdst = (((long long)bb * SEQL + by * 128 + row) * EMB + hh * HD) + word * 2;
        *(uint32_t*)(ohi + gdst) = wh;
        *(uint32_t*)(olo + gdst) = wl;
    }
}

// ---------------------------------------------------------------------------
// norm_attn: stream attn rows in place, scaling by inv. Pure DRAM kernel;
// overlaps the tensor-bound out-projection.
// ---------------------------------------------------------------------------
__global__ __launch_bounds__(256)
void norm_attn(float* __restrict__ attn, const float* __restrict__ inv, int z0) {
    const int bz = blockIdx.y + z0;
    const int r0 = blockIdx.x * 4;
    const int tid = threadIdx.x;
    float* zbase = attn + (long long)bz * SEQL * SEQL;
    #pragma unroll
    for (int i = 0; i < 4; i++) {
        const int r = r0 + i;
        const float iv = inv[(long long)bz * SEQL + r];
        float4* p = (float4*)(zbase + (long long)r * SEQL) + tid;
        float4 v = *p;
        v.x *= iv; v.y *= iv; v.z *= iv; v.w *= iv;
        *p = v;
    }
}

// ---------------------------------------------------------------------------
// fp32 -> bf16 hi/lo split
// ---------------------------------------------------------------------------
__global__ void split_hilo(const float* __restrict__ src,
                           __nv_bfloat16* __restrict__ hi,
                           __nv_bfloat16* __restrict__ lo, int n) {
    int i = blockIdx.x * 256 + threadIdx.x;
    if (i < n) {
        float v = src[i];
        __nv_bfloat16 h = __float2bfloat16(v);
        hi[i] = h;
        lo[i] = __float2bfloat16(v - __bfloat162float(h));
    }
}

// ---------------------------------------------------------------------------
// Launch: 3 lanes, only 2 created streams (proven footprint).
// stream 0: weight splits -> m3A (wait fusedA) -> m3B (wait fusedB)
// sA: split(xA) -> m0A -> fusedA -> normA
// sB: split(xB) -> m0B -> fusedB -> normB
// ---------------------------------------------------------------------------
extern "C" void kernel_launch(void* const* d_in, const int* in_sizes, int n_in,
                              void* d_out, int out_size) {
    (void)in_sizes; (void)n_in; (void)out_size;
    const float* x      = (const float*)d_in[0];
    const float* w_qkv  = (const float*)d_in[1];
    const float* w_proj = (const float*)d_in[2];
    const float* b_proj = (const float*)d_in[3];

    float* out  = (float*)d_out;
    float* attn = out + (long long)ROWS * EMB;

    __nv_bfloat16 *xh, *xl, *wqh, *wql, *wph, *wpl, *qh, *ql, *ohh, *ohl;
    float* inv;
    cudaGetSymbolAddress((void**)&xh,  g_x_hi);    cudaGetSymbolAddress((void**)&xl,  g_x_lo);
    cudaGetSymbolAddress((void**)&wqh, g_wqkv_hi); cudaGetSymbolAddress((void**)&wql, g_wqkv_lo);
    cudaGetSymbolAddress((void**)&wph, g_wp_hi);   cudaGetSymbolAddress((void**)&wpl, g_wp_lo);
    cudaGetSymbolAddress((void**)&qh,  g_qkv_hi);  cudaGetSymbolAddress((void**)&ql,  g_qkv_lo);
    cudaGetSymbolAddress((void**)&ohh, g_oh_hi);   cudaGetSymbolAddress((void**)&ohl, g_oh_lo);
    cudaGetSymbolAddress((void**)&inv, g_inv);

    constexpr int SMBIG = 3 * 61440;              // 184320
    constexpr int SMFA  = 2 * 18432 + 2 * 36864;  // 110592
    constexpr int HALF_X = ROWS * EMB / 2;

    static cudaStream_t sA = nullptr, sB = nullptr;
    static cudaEvent_t evWq = nullptr, evAf = nullptr, evBf = nullptr;
    static cudaEvent_t evA = nullptr, evB = nullptr;
    static bool init_done = false;
    if (!init_done) {
        cudaFuncSetAttribute(gemm_big<0>, cudaFuncAttributeMaxDynamicSharedMemorySize, SMBIG);
        cudaFuncSetAttribute(gemm_big<3>, cudaFuncAttributeMaxDynamicSharedMemorySize, SMBIG);
        cudaFuncSetAttribute(fused_attn, cudaFuncAttributeMaxDynamicSharedMemorySize, SMFA);
        cudaStreamCreateWithFlags(&sA, cudaStreamNonBlocking);
        cudaStreamCreateWithFlags(&sB, cudaStreamNonBlocking);
        cudaEventCreateWithFlags(&evWq, cudaEventDisableTiming);
        cudaEventCreateWithFlags(&evAf, cudaEventDisableTiming);
        cudaEventCreateWithFlags(&evBf, cudaEventDisableTiming);
        cudaEventCreateWithFlags(&evA,  cudaEventDisableTiming);
        cudaEventCreateWithFlags(&evB,  cudaEventDisableTiming);
        init_done = true;
    }

    // stream 0: weight splits (wp split stays ahead of m3 in program order)
    split_hilo<<<(QKVC*EMB + 255)/256, 256>>>(w_qkv, wqh, wql, QKVC*EMB);
    cudaEventRecord(evWq, 0);
    split_hilo<<<(EMB*EMB + 255)/256, 256>>>(w_proj, wph, wpl, EMB*EMB);

    // --- pipeline A: batches 0-3 ---
    split_hilo<<<(HALF_X + 255)/256, 256, 0, sA>>>(x, xh, xl, HALF_X);
    cudaStreamWaitEvent(sA, evWq, 0);
    gemm_big<0><<<dim3(QKVC/128, 16), 256, SMBIG, sA>>>(
        xh, xl, wqh, wql, nullptr, qh, ql, nullptr, 0);
    fused_attn<<<dim3(8, 48), 256, SMFA, sA>>>(qh, ql, attn, ohh, ohl, inv, 0);
    cudaEventRecord(evAf, sA);
    norm_attn<<<dim3(SEQL/4, 48), 256, 0, sA>>>(attn, inv, 0);
    cudaEventRecord(evA, sA);

    // --- pipeline B: batches 4-7 ---
    split_hilo<<<(HALF_X + 255)/256, 256, 0, sB>>>(x + HALF_X, xh + HALF_X, xl + HALF_X, HALF_X);
    cudaStreamWaitEvent(sB, evWq, 0);
    gemm_big<0><<<dim3(QKVC/128, 16), 256, SMBIG, sB>>>(
        xh, xl, wqh, wql, nullptr, qh, ql, nullptr, 16);
    fused_attn<<<dim3(8, 48), 256, SMFA, sB>>>(qh, ql, attn, ohh, ohl, inv, 48);
    cudaEventRecord(evBf, sB);
    norm_attn<<<dim3(SEQL/4, 48), 256, 0, sB>>>(attn, inv, 48);
    cudaEventRecord(evB, sB);

    // stream 0: out-projection halves, each gated only on its fused_attn
    cudaStreamWaitEvent(0, evAf, 0);
    gemm_big<3><<<dim3(EMB/128, 16), 256, SMBIG>>>(
        ohh, ohl, wph, wpl, out, nullptr, nullptr, b_proj, 0);
    cudaStreamWaitEvent(0, evBf, 0);
    gemm_big<3><<<dim3(EMB/128, 16), 256, SMBIG>>>(
        ohh, ohl, wph, wpl, out, nullptr, nullptr, b_proj, 16);

    // join norm branches into the caller's stream
    cudaStreamWaitEvent(0, evA, 0);
    cudaStreamWaitEvent(0, evB, 0);
}